// round 7
// baseline (speedup 1.0000x reference)
#include <cuda_runtime.h>
#include <cstdint>

#define ML   80
#define LD   10
#define BSZ  512
#define HID  32
#define ST   10
#define NKEYS 880        // ML*(ST+1)
#define GPI  171         // 3-batch groups per chain i: ceil(512/3)

__device__ uint2 g_keys[NKEYS];           // partitionable-split subkeys
__device__ float g_acc[BSZ * ML * HID];   // 5.2 MB exclusive prefix of z@W1

// ---------------- f32x2 packed helpers (PTX-only on Blackwell) ----------------
__device__ __forceinline__ unsigned long long pk2(float lo, float hi) {
    unsigned long long r;
    asm("mov.b64 %0, {%1, %2};" : "=l"(r) : "f"(lo), "f"(hi));
    return r;
}
__device__ __forceinline__ void upk2(unsigned long long v, float &lo, float &hi) {
    asm("mov.b64 {%0, %1}, %2;" : "=f"(lo), "=f"(hi) : "l"(v));
}
__device__ __forceinline__ unsigned long long fma2(unsigned long long a,
                                                   unsigned long long b,
                                                   unsigned long long c) {
    unsigned long long d;
    asm("fma.rn.f32x2 %0, %1, %2, %3;" : "=l"(d) : "l"(a), "l"(b), "l"(c));
    return d;
}
__device__ __forceinline__ unsigned long long add2(unsigned long long a,
                                                   unsigned long long b) {
    unsigned long long d;
    asm("add.rn.f32x2 %0, %1, %2;" : "=l"(d) : "l"(a), "l"(b));
    return d;
}

// ---------------- threefry2x32-20 ----------------
__device__ __forceinline__ uint32_t rotl32(uint32_t x, int r) {
    return __funnelshift_l(x, x, r);
}
__device__ __forceinline__ void threefry2x32(uint32_t k1, uint32_t k2,
                                             uint32_t &x0, uint32_t &x1) {
    uint32_t k3 = k1 ^ k2 ^ 0x1BD11BDAu;
    x0 += k1; x1 += k2;
#define R1(r) { x0 += x1; x1 = rotl32(x1, r); x1 ^= x0; }
#define RA R1(13) R1(15) R1(26) R1(6)
#define RB R1(17) R1(29) R1(16) R1(24)
    RA  x0 += k2; x1 += k3 + 1u;
    RB  x0 += k3; x1 += k1 + 2u;
    RA  x0 += k1; x1 += k2 + 3u;
    RB  x0 += k2; x1 += k3 + 4u;
    RA  x0 += k3; x1 += k1 + 5u;
#undef R1
#undef RA
#undef RB
}

__device__ __forceinline__ float bits_to_normal(uint32_t bits) {
    const float lo = __uint_as_float(0xBF7FFFFFu);       // nextafterf(-1, 0)
    float f = __fsub_rn(__uint_as_float((bits >> 9) | 0x3F800000u), 1.0f);
    float span = __fsub_rn(1.0f, lo);                    // == 2.0f
    float u = __fadd_rn(__fmul_rn(f, span), lo);
    u = fmaxf(u, lo);
    return __fmul_rn(1.41421356237309515f, erfinvf(u));
}

__device__ __forceinline__ float draw_normal(uint2 key, uint32_t m) {
    uint32_t x0 = 0u, x1 = m;
    threefry2x32(key.x, key.y, x0, x1);
    return bits_to_normal(x0 ^ x1);
}

// ---- k_init: blocks [0,256) prefscan (2 batches each), [256,260) key table ----
__global__ void __launch_bounds__(256) k_init(const float* __restrict__ z_mean,
                                              const float* __restrict__ W1) {
    int tid = threadIdx.x;

    if (blockIdx.x >= 256) {
        int j = (blockIdx.x - 256) * 256 + tid;
        if (j < NKEYS) {
            uint32_t x0 = 0u, x1 = (uint32_t)j;   // partitionable split of key(1337)
            threefry2x32(0u, 1337u, x0, x1);
            g_keys[j] = make_uint2(x0, x1);
        }
        return;
    }

    __shared__ float zb[2 * ML * LD];
    __shared__ float sp[2][ML * HID];
    int b0 = blockIdx.x * 2;

    for (int p = tid; p < 2 * ML * LD; p += 256)
        zb[p] = z_mean[b0 * ML * LD + p];
    __syncthreads();

    // P[l][j] for both batches; W1 element loaded once, used twice
#pragma unroll
    for (int r = 0; r < 10; r++) {
        int p = tid + 256 * r;
        int l = p >> 5, j = p & 31;
        float a0 = 0.f, a1 = 0.f;
#pragma unroll
        for (int d = 0; d < LD; d++) {
            float w = W1[(l * LD + d) * HID + j];
            a0 = fmaf(zb[l * LD + d],           w, a0);
            a1 = fmaf(zb[ML * LD + l * LD + d], w, a1);
        }
        sp[0][p] = a0;
        sp[1][p] = a1;
    }
    __syncthreads();

    // serial exclusive scan over l: 64 lanes = 2 batches x 32 j, write g_acc directly
    if (tid < 64) {
        int bi = tid >> 5, j = tid & 31;
        const float* spb = sp[bi];
        float* dst = g_acc + (b0 + bi) * ML * HID + j;
        float run = 0.f;
#pragma unroll 8
        for (int l = 0; l < ML; l++) {
            float v = spb[l * HID + j];
            dst[l * HID] = run;
            run += v;
        }
    }
}

// ---------------- k_main: fused noise + sim, f32x2 math, one warp per (i, 3-batch) ----------------
__global__ void __launch_bounds__(128, 6) k_main(
    const float* __restrict__ z_mean, const float* __restrict__ z_log_var,
    const float* __restrict__ W1, const float* __restrict__ b1,
    const float* __restrict__ W2, const float* __restrict__ b2,
    float* __restrict__ out)
{
    __shared__ __align__(16) unsigned long long s_x01[4][12];  // (task0, task1) per d
    __shared__ __align__(16) unsigned long long s_x23[4][12];  // (task2, task2) per d
    __shared__ __align__(16) float s_rh[4][3][36];             // padded rows
    __shared__ __align__(16) float s_w2[LD][36];               // W2 col d in j-order

    int tid = threadIdx.x;
    int w = tid >> 5;
    int lane = tid & 31;

    // block-shared W2 transpose: s_w2[d][j] = W2[j*10+d]
    for (int p = tid; p < HID * LD; p += 128)
        s_w2[p % LD][p / LD] = W2[p];
    __syncthreads();

    int gw = blockIdx.x * 4 + w;       // 13680 warps exactly (80*171)
    int i = gw / GPI;
    int g = gw - i * GPI;
    int bs = 3 * g;

    // ---- (k,d)-role indices ----
    int kk = lane / LD;                      // 0..3 (lanes 30,31 -> 3)
    int d  = lane - kk * LD;
    int kc = min(kk, 2);
    bool kval = (kk < 3) && (bs + kk < BSZ);
    int bk2 = min(bs + kc, BSZ - 1);
    int zi = (bk2 * ML + i) * LD + d;
    uint32_t m = (uint32_t)(bk2 * LD + d);
    const uint2* kp = g_keys + i * 11;

    // ---- j-role constants (lane = hidden unit j), packed ----
    unsigned long long w1p[LD];
#pragma unroll
    for (int dd = 0; dd < LD; dd++) {
        float v = W1[(i * LD + dd) * HID + lane];
        w1p[dd] = pk2(v, v);
    }
    float w1t = W1[800 * HID + lane];
    float b1v = b1[lane];
    float a0 = g_acc[(min(bs + 0, BSZ - 1) * ML + i) * HID + lane] + b1v;
    float a1 = g_acc[(min(bs + 1, BSZ - 1) * ML + i) * HID + lane] + b1v;
    float a2 = g_acc[(min(bs + 2, BSZ - 1) * ML + i) * HID + lane] + b1v;

    // h-base with incremental t*w1t: hb = acc + t_s*w1t, advanced by 0.1*w1t per step
    float ti = (float)i;
    float tb0 = fmaf(ti, w1t, a0);
    float tb1 = fmaf(ti, w1t, a1);
    float tb2 = fmaf(ti, w1t, a2);
    unsigned long long hb01 = pk2(tb0, tb1);
    unsigned long long hb23 = pk2(tb2, tb2);
    float dtw = 0.1f * w1t;
    unsigned long long dtp = pk2(dtw, dtw);

    // ---- (k,d)-role constants ----
    float mu   = z_mean[zi];
    float sig  = expf(z_log_var[zi]);
    float sstd = sqrtf(sig);
    unsigned long long b2vp = pk2(b2[d], 0.f);

    float xt  = mu + sstd * draw_normal(kp[0], m);
    float err = 0.f;
    float halfsig = 0.5f * sig;
    float ssdt = sstd * 0.31622776601683794f;   // sstd * sqrt(DT)
    float rstd = 1.0f / sstd;

    if (kk < 2)       ((float*)&s_x01[w][d])[kk] = xt;
    else if (kk == 2) s_x23[w][d] = pk2(xt, xt);
    __syncwarp();

#pragma unroll
    for (int s = 0; s < ST; s++) {
        // independent alu-pipe work: next noise draw overlaps the fma chains
        float nv = draw_normal(kp[s + 1], m);

        // h-phase: lane = j; 4 parallel packed chains, LDS.128 broadcasts
        const ulonglong2* xp01 = (const ulonglong2*)&s_x01[w][0];
        const ulonglong2* xp23 = (const ulonglong2*)&s_x23[w][0];
        unsigned long long h01a = hb01, h01b = pk2(0.f, 0.f);
        unsigned long long h23a = hb23, h23b = pk2(0.f, 0.f);
#pragma unroll
        for (int q = 0; q < 5; q++) {
            ulonglong2 xa = xp01[q];
            ulonglong2 xb = xp23[q];
            h01a = fma2(xa.x, w1p[2 * q],     h01a);
            h01b = fma2(xa.y, w1p[2 * q + 1], h01b);
            h23a = fma2(xb.x, w1p[2 * q],     h23a);
            h23b = fma2(xb.y, w1p[2 * q + 1], h23b);
        }
        unsigned long long h01 = add2(h01a, h01b);
        unsigned long long h23 = add2(h23a, h23b);
        float h0, h1, h2, hx;
        upk2(h01, h0, h1);
        upk2(h23, h2, hx);
        s_rh[w][0][lane] = fmaxf(h0, 0.f);
        s_rh[w][1][lane] = fmaxf(h1, 0.f);
        s_rh[w][2][lane] = fmaxf(h2, 0.f);
        __syncwarp();

        // sc-phase: lane = (k,d); rh row + W2 column, both smem, packed math
        const ulonglong2* rp = (const ulonglong2*)s_rh[w][kc];
        const ulonglong2* wp = (const ulonglong2*)s_w2[d];
        unsigned long long sA = b2vp;
        unsigned long long sB = pk2(0.f, 0.f);
#pragma unroll
        for (int q = 0; q < 8; q++) {
            ulonglong2 rv = rp[q];
            ulonglong2 wv = wp[q];
            sA = fma2(rv.x, wv.x, sA);
            sB = fma2(rv.y, wv.y, sB);
        }
        float p0, p1, p2, p3;
        upk2(sA, p0, p1);
        upk2(sB, p2, p3);
        float sc = (p0 + p1) + (p2 + p3);

        err += fabsf((mu - xt) * rstd - sc);
        xt = fmaf(halfsig, sc, xt) + ssdt * nv;
        if (kk < 2)       ((float*)&s_x01[w][d])[kk] = xt;
        else if (kk == 2) s_x23[w][d] = pk2(xt, xt);
        hb01 = add2(hb01, dtp);
        hb23 = add2(hb23, dtp);
        __syncwarp();
    }

    if (kval) {
        out[zi] = xt;                         // sequence
        out[BSZ * ML * LD + zi] = err;        // score_error
    }
}

// ---------------- launch ----------------
extern "C" void kernel_launch(void* const* d_in, const int* in_sizes, int n_in,
                              void* d_out, int out_size) {
    const float* z_mean    = (const float*)d_in[0];
    const float* z_log_var = (const float*)d_in[1];
    const float* W1        = (const float*)d_in[2];
    const float* b1        = (const float*)d_in[3];
    const float* W2        = (const float*)d_in[4];
    const float* b2        = (const float*)d_in[5];
    float* out = (float*)d_out;

    k_init<<<260, 256>>>(z_mean, W1);                                          // 256 scan + 4 key blocks
    k_main<<<(ML * GPI) / 4, 128>>>(z_mean, z_log_var, W1, b1, W2, b2, out);   // 3420 blocks
}

// round 8
// speedup vs baseline: 1.3204x; 1.3204x over previous
#include <cuda_runtime.h>
#include <cstdint>

#define ML   80
#define LD   10
#define BSZ  512
#define HID  32
#define ST   10
#define NKEYS 880        // ML*(ST+1)
#define GPI  171         // 3-batch groups per chain i: ceil(512/3)

__device__ uint2 g_keys[NKEYS];           // partitionable-split subkeys
__device__ float g_acc[BSZ * ML * HID];   // 5.2 MB exclusive prefix of z@W1

// ---------------- f32x2 packed helpers (PTX-only on Blackwell) ----------------
__device__ __forceinline__ unsigned long long pk2(float lo, float hi) {
    unsigned long long r;
    asm("mov.b64 %0, {%1, %2};" : "=l"(r) : "f"(lo), "f"(hi));
    return r;
}
__device__ __forceinline__ void upk2(unsigned long long v, float &lo, float &hi) {
    asm("mov.b64 {%0, %1}, %2;" : "=f"(lo), "=f"(hi) : "l"(v));
}
__device__ __forceinline__ unsigned long long fma2(unsigned long long a,
                                                   unsigned long long b,
                                                   unsigned long long c) {
    unsigned long long d;
    asm("fma.rn.f32x2 %0, %1, %2, %3;" : "=l"(d) : "l"(a), "l"(b), "l"(c));
    return d;
}

// ---------------- threefry2x32-20 ----------------
__device__ __forceinline__ uint32_t rotl32(uint32_t x, int r) {
    return __funnelshift_l(x, x, r);
}
__device__ __forceinline__ void threefry2x32(uint32_t k1, uint32_t k2,
                                             uint32_t &x0, uint32_t &x1) {
    uint32_t k3 = k1 ^ k2 ^ 0x1BD11BDAu;
    x0 += k1; x1 += k2;
#define R1(r) { x0 += x1; x1 = rotl32(x1, r); x1 ^= x0; }
#define RA R1(13) R1(15) R1(26) R1(6)
#define RB R1(17) R1(29) R1(16) R1(24)
    RA  x0 += k2; x1 += k3 + 1u;
    RB  x0 += k3; x1 += k1 + 2u;
    RA  x0 += k1; x1 += k2 + 3u;
    RB  x0 += k2; x1 += k3 + 4u;
    RA  x0 += k3; x1 += k1 + 5u;
#undef R1
#undef RA
#undef RB
}

__device__ __forceinline__ float bits_to_normal(uint32_t bits) {
    const float lo = __uint_as_float(0xBF7FFFFFu);       // nextafterf(-1, 0)
    float f = __fsub_rn(__uint_as_float((bits >> 9) | 0x3F800000u), 1.0f);
    float span = __fsub_rn(1.0f, lo);                    // == 2.0f
    float u = __fadd_rn(__fmul_rn(f, span), lo);
    u = fmaxf(u, lo);
    return __fmul_rn(1.41421356237309515f, erfinvf(u));
}

__device__ __forceinline__ float draw_normal(uint2 key, uint32_t m) {
    uint32_t x0 = 0u, x1 = m;
    threefry2x32(key.x, key.y, x0, x1);
    return bits_to_normal(x0 ^ x1);
}

// ---- k_init: blocks [0,128) prefscan (4 batches each), [128,132) key table ----
__global__ void __launch_bounds__(256) k_init(const float* __restrict__ z_mean,
                                              const float* __restrict__ W1) {
    int tid = threadIdx.x;

    if (blockIdx.x >= 128) {
        int j = (blockIdx.x - 128) * 256 + tid;
        if (j < NKEYS) {
            uint32_t x0 = 0u, x1 = (uint32_t)j;   // partitionable split of key(1337)
            threefry2x32(0u, 1337u, x0, x1);
            g_keys[j] = make_uint2(x0, x1);
        }
        return;
    }

    __shared__ float zb[4 * ML * LD];          // 12.8 KB
    __shared__ float sp[4][ML * HID];          // 40 KB
    int b0 = blockIdx.x * 4;

    // coalesced float4 loads of 4 batches of z_mean
    const float4* zsrc = (const float4*)(z_mean + b0 * ML * LD);
    float4* zdst = (float4*)zb;
    for (int p = tid; p < ML * LD; p += 256)   // 800 float4 = 3200 floats
        zdst[p] = zsrc[p];
    __syncthreads();

    // P[l][j] for 4 batches; W1 element loaded once, used 4x
#pragma unroll
    for (int r = 0; r < 10; r++) {
        int p = tid + 256 * r;                 // 2560 positions (l, j)
        int l = p >> 5, j = p & 31;
        float a0 = 0.f, a1 = 0.f, a2 = 0.f, a3 = 0.f;
#pragma unroll
        for (int d = 0; d < LD; d++) {
            float w = W1[(l * LD + d) * HID + j];
            int zo = l * LD + d;
            a0 = fmaf(zb[zo],               w, a0);
            a1 = fmaf(zb[ML * LD + zo],     w, a1);
            a2 = fmaf(zb[2 * ML * LD + zo], w, a2);
            a3 = fmaf(zb[3 * ML * LD + zo], w, a3);
        }
        sp[0][p] = a0;
        sp[1][p] = a1;
        sp[2][p] = a2;
        sp[3][p] = a3;
    }
    __syncthreads();

    // serial exclusive scan over l: 128 lanes = 4 batches x 32 j, write g_acc
    if (tid < 128) {
        int bi = tid >> 5, j = tid & 31;
        const float* spb = sp[bi];
        float* dst = g_acc + (b0 + bi) * ML * HID + j;
        float run = 0.f;
#pragma unroll 8
        for (int l = 0; l < ML; l++) {
            float v = spb[l * HID + j];
            dst[l * HID] = run;
            run += v;
        }
    }
}

// ---------------- k_main: fused noise + sim, f32x2 math, one warp per (i, 3-batch) ----------------
__global__ void __launch_bounds__(128, 6) k_main(
    const float* __restrict__ z_mean, const float* __restrict__ z_log_var,
    const float* __restrict__ W1, const float* __restrict__ b1,
    const float* __restrict__ W2, const float* __restrict__ b2,
    float* __restrict__ out)
{
    __shared__ __align__(16) float s_xt[4][3][12];   // xt per task, d-contiguous
    __shared__ __align__(16) float s_rh[4][3][36];   // padded rows: conflict-free

    int tid = threadIdx.x;
    int w = tid >> 5;
    int lane = tid & 31;

    int gw = blockIdx.x * 4 + w;       // 13680 warps exactly (80*171)
    int i = gw / GPI;
    int g = gw - i * GPI;
    int bs = 3 * g;

    // ---- (k,d)-role indices ----
    int kk = lane / LD;                      // 0..3 (lanes 30,31 -> 3)
    int d  = lane - kk * LD;
    int kc = min(kk, 2);
    bool kval = (kk < 3) && (bs + kk < BSZ);
    int bk2 = min(bs + kc, BSZ - 1);
    int zi = (bk2 * ML + i) * LD + d;
    uint32_t m = (uint32_t)(bk2 * LD + d);
    const uint2* kp = g_keys + i * 11;

    // ---- j-role constants (lane = hidden unit j); W1 row packed over d ----
    unsigned long long w1p[5];
#pragma unroll
    for (int q = 0; q < 5; q++) {
        float vlo = W1[(i * LD + 2 * q)     * HID + lane];
        float vhi = W1[(i * LD + 2 * q + 1) * HID + lane];
        w1p[q] = pk2(vlo, vhi);
    }
    float w1t = W1[800 * HID + lane];
    float b1v = b1[lane];
    float ti = (float)i;
    // hb_k = acc_k + b1 + t*w1t, advanced incrementally by 0.1*w1t per step
    float hb0 = fmaf(ti, w1t, g_acc[(min(bs + 0, BSZ - 1) * ML + i) * HID + lane] + b1v);
    float hb1 = fmaf(ti, w1t, g_acc[(min(bs + 1, BSZ - 1) * ML + i) * HID + lane] + b1v);
    float hb2 = fmaf(ti, w1t, g_acc[(min(bs + 2, BSZ - 1) * ML + i) * HID + lane] + b1v);
    float dtw = 0.1f * w1t;

    // ---- (k,d)-role constants, W2 column packed in register pairs ----
    float mu   = z_mean[zi];
    float sig  = expf(z_log_var[zi]);
    float sstd = sqrtf(sig);
    float b2v  = b2[d];
    unsigned long long w2p[16];
#pragma unroll
    for (int p = 0; p < 16; p++)
        w2p[p] = pk2(W2[(2 * p) * LD + d], W2[(2 * p + 1) * LD + d]);

    float xt  = mu + sstd * draw_normal(kp[0], m);
    float err = 0.f;
    float halfsig = 0.5f * sig;
    float ssdt = sstd * 0.31622776601683794f;   // sstd * sqrt(DT)
    float rstd = 1.0f / sstd;

    if (kk < 3) s_xt[w][kk][d] = xt;
    __syncwarp();

#pragma unroll
    for (int s = 0; s < ST; s++) {
        // independent alu-pipe work: next noise draw overlaps the fma chains
        float nv = draw_normal(kp[s + 1], m);

        // h-phase: lane = j; 3 independent 5-deep packed chains (packed over d)
#pragma unroll
        for (int k = 0; k < 3; k++) {
            ulonglong2 xa = *(const ulonglong2*)&s_xt[w][k][0];   // d0..3
            ulonglong2 xb = *(const ulonglong2*)&s_xt[w][k][4];   // d4..7
            unsigned long long xc = *(const unsigned long long*)&s_xt[w][k][8]; // d8,9
            float hbk = (k == 0) ? hb0 : (k == 1) ? hb1 : hb2;
            unsigned long long h = fma2(xa.x, w1p[0], pk2(hbk, 0.f));
            h = fma2(xa.y, w1p[1], h);
            h = fma2(xb.x, w1p[2], h);
            h = fma2(xb.y, w1p[3], h);
            h = fma2(xc,   w1p[4], h);
            float hlo, hhi;
            upk2(h, hlo, hhi);
            s_rh[w][k][lane] = fmaxf(hlo + hhi, 0.f);
        }
        __syncwarp();

        // sc-phase: lane = (k,d); rh row packed over j, W2 column in registers
        const ulonglong2* rp = (const ulonglong2*)s_rh[w][kc];
        unsigned long long sA = pk2(b2v, 0.f);
        unsigned long long sB = pk2(0.f, 0.f);
#pragma unroll
        for (int q = 0; q < 8; q++) {
            ulonglong2 rv = rp[q];
            sA = fma2(rv.x, w2p[2 * q],     sA);
            sB = fma2(rv.y, w2p[2 * q + 1], sB);
        }
        float p0, p1, p2, p3;
        upk2(sA, p0, p1);
        upk2(sB, p2, p3);
        float sc = (p0 + p1) + (p2 + p3);

        err += fabsf((mu - xt) * rstd - sc);
        xt = fmaf(halfsig, sc, xt) + ssdt * nv;
        if (kk < 3) s_xt[w][kk][d] = xt;
        hb0 += dtw;
        hb1 += dtw;
        hb2 += dtw;
        __syncwarp();
    }

    if (kval) {
        out[zi] = xt;                         // sequence
        out[BSZ * ML * LD + zi] = err;        // score_error
    }
}

// ---------------- launch ----------------
extern "C" void kernel_launch(void* const* d_in, const int* in_sizes, int n_in,
                              void* d_out, int out_size) {
    const float* z_mean    = (const float*)d_in[0];
    const float* z_log_var = (const float*)d_in[1];
    const float* W1        = (const float*)d_in[2];
    const float* b1        = (const float*)d_in[3];
    const float* W2        = (const float*)d_in[4];
    const float* b2        = (const float*)d_in[5];
    float* out = (float*)d_out;

    k_init<<<132, 256>>>(z_mean, W1);                                          // 128 scan + 4 key blocks
    k_main<<<(ML * GPI) / 4, 128>>>(z_mean, z_log_var, W1, b1, W2, b2, out);   // 3420 blocks
}